// round 15
// baseline (speedup 1.0000x reference)
#include <cuda_runtime.h>
#include <cuda_bf16.h>
#include <cstdint>
#include <math.h>

#define N 8192
#define D 256
#define H 64
#define MARGIN 100.0f
#define GAMMA 2.0f

// ---------------------------------------------------------------------------
// Device scratch (no allocs allowed)
// ---------------------------------------------------------------------------
__device__ float          g_tn32[N * D];      // target_norm fp32 (for exact diag)
__device__ __nv_bfloat16  g_tnb[N * D];       // target_norm bf16 (GEMM B)
__device__ __nv_bfloat16  g_pnb[N * D];       // pred_norm bf16 (GEMM A)
__device__ float          g_diag[N];          // exact <pred_norm_i, target_norm_i>
__device__ float          g_part[2 * N * 10]; // per-half top-10 dots (descending)
__device__ float          g_terms[N];         // per-row loss terms

// ---------------------------------------------------------------------------
// PTX helpers — base-target instructions ONLY (sm_103 PTX target, no 'a')
// ---------------------------------------------------------------------------
__device__ __forceinline__ uint32_t smem_u32(const void* p) {
    uint32_t a;
    asm("{ .reg .u64 t; cvta.to.shared.u64 t, %1; cvt.u32.u64 %0, t; }"
        : "=r"(a) : "l"(p));
    return a;
}

__device__ __forceinline__ void ldmatrix_x4(uint32_t& r0, uint32_t& r1,
                                            uint32_t& r2, uint32_t& r3,
                                            uint32_t addr) {
    asm volatile("ldmatrix.sync.aligned.m8n8.x4.shared.b16 {%0,%1,%2,%3}, [%4];"
                 : "=r"(r0), "=r"(r1), "=r"(r2), "=r"(r3) : "r"(addr));
}

__device__ __forceinline__ void mma_bf16(float* d, const uint32_t* a, const uint32_t* b) {
    asm volatile(
        "mma.sync.aligned.m16n8k16.row.col.f32.bf16.bf16.f32 "
        "{%0,%1,%2,%3}, {%4,%5,%6,%7}, {%8,%9}, {%0,%1,%2,%3};"
        : "+f"(d[0]), "+f"(d[1]), "+f"(d[2]), "+f"(d[3])
        : "r"(a[0]), "r"(a[1]), "r"(a[2]), "r"(a[3]), "r"(b[0]), "r"(b[1]));
}

#define CP_ASYNC16(dst, src) \
    asm volatile("cp.async.cg.shared.global [%0], [%1], 16;" :: "r"(dst), "l"(src))
#define CP_COMMIT() asm volatile("cp.async.commit_group;" ::: "memory")
#define CP_WAIT1()  asm volatile("cp.async.wait_group 1;" ::: "memory")
#define CP_WAIT0()  asm volatile("cp.async.wait_group 0;" ::: "memory")

// ---------------------------------------------------------------------------
// Kernel 1: L2-normalize target rows. Warp per row. Launched twice (half grid
// each) so the GEMM is the 4th kernel launch (ncu captures launch #4).
// ---------------------------------------------------------------------------
__global__ __launch_bounds__(256) void target_norm_kernel(const float* __restrict__ tgt,
                                                          int rowbase) {
    const int wid = threadIdx.x >> 5, lane = threadIdx.x & 31;
    const int row = rowbase + blockIdx.x * 8 + wid;
    const float* rp = tgt + (size_t)row * D + lane * 8;
    const float4 v0 = *(const float4*)rp;
    const float4 v1 = *(const float4*)(rp + 4);
    float s = v0.x * v0.x + v0.y * v0.y + v0.z * v0.z + v0.w * v0.w
            + v1.x * v1.x + v1.y * v1.y + v1.z * v1.z + v1.w * v1.w;
#pragma unroll
    for (int o = 16; o > 0; o >>= 1) s += __shfl_xor_sync(0xFFFFFFFF, s, o);
    const float inv = 1.0f / fmaxf(sqrtf(s), 1e-12f);

    float4 o0, o1;
    o0.x = v0.x * inv; o0.y = v0.y * inv; o0.z = v0.z * inv; o0.w = v0.w * inv;
    o1.x = v1.x * inv; o1.y = v1.y * inv; o1.z = v1.z * inv; o1.w = v1.w * inv;
    float* wp = g_tn32 + (size_t)row * D + lane * 8;
    *(float4*)wp = o0;
    *(float4*)(wp + 4) = o1;

    union { __nv_bfloat16 h[8]; uint4 u; } pk;
    pk.h[0] = __float2bfloat16(o0.x); pk.h[1] = __float2bfloat16(o0.y);
    pk.h[2] = __float2bfloat16(o0.z); pk.h[3] = __float2bfloat16(o0.w);
    pk.h[4] = __float2bfloat16(o1.x); pk.h[5] = __float2bfloat16(o1.y);
    pk.h[6] = __float2bfloat16(o1.z); pk.h[7] = __float2bfloat16(o1.w);
    *(uint4*)(g_tnb + (size_t)row * D + lane * 8) = pk.u;
}

// ---------------------------------------------------------------------------
// Kernel 2: batched MLP + normalize + exact diag dot.
// 32 rows/block, 256 threads, weights staged in SMEM (168 KB dynamic).
// ---------------------------------------------------------------------------
#define MR 32
__global__ __launch_bounds__(256) void mlp_kernel(const float* __restrict__ x,
                                                  const float* __restrict__ W1,
                                                  const float* __restrict__ b1,
                                                  const float* __restrict__ W2,
                                                  const float* __restrict__ b2) {
    extern __shared__ float fsm[];
    float* W1s = fsm;                 // [256][64]  16384 floats
    float* W2s = fsm + 16384;         // [64][256]  16384 floats
    float* xs  = fsm + 32768;         // [32][256]  8192 floats
    float* hs  = fsm + 40960;         // [32][64]   2048 floats
    float* ss  = fsm;                 // alias over W1s after it is no longer read
    float* qq  = fsm + 8192;
    __shared__ float invs[MR], dgs[MR];

    const int tid = threadIdx.x;
    const int row0 = blockIdx.x * MR;

    {
        const float4* w1 = (const float4*)W1;
        const float4* w2 = (const float4*)W2;
        const float4* xg = (const float4*)(x + (size_t)row0 * D);
#pragma unroll
        for (int it = 0; it < 16; it++) ((float4*)W1s)[it * 256 + tid] = w1[it * 256 + tid];
#pragma unroll
        for (int it = 0; it < 16; it++) ((float4*)W2s)[it * 256 + tid] = w2[it * 256 + tid];
#pragma unroll
        for (int it = 0; it < 8; it++) ((float4*)xs)[it * 256 + tid] = xg[it * 256 + tid];
    }
    __syncthreads();

    // Phase B: hidden = relu(x @ W1 + b1). 512 (r,jg) tasks, 2 per thread.
#pragma unroll
    for (int t2 = 0; t2 < 2; t2++) {
        const int task = t2 * 256 + tid;
        const int r = task >> 4;
        const int jg = task & 15;
        float acc0 = 0.f, acc1 = 0.f, acc2 = 0.f, acc3 = 0.f;
        for (int kk = 0; kk < D; kk += 4) {
            const float4 xv = *(const float4*)&xs[r * D + kk];
            const float4 w0 = *(const float4*)&W1s[(kk + 0) * H + jg * 4];
            const float4 w1v = *(const float4*)&W1s[(kk + 1) * H + jg * 4];
            const float4 w2v = *(const float4*)&W1s[(kk + 2) * H + jg * 4];
            const float4 w3 = *(const float4*)&W1s[(kk + 3) * H + jg * 4];
            acc0 = fmaf(xv.x, w0.x, acc0); acc1 = fmaf(xv.x, w0.y, acc1);
            acc2 = fmaf(xv.x, w0.z, acc2); acc3 = fmaf(xv.x, w0.w, acc3);
            acc0 = fmaf(xv.y, w1v.x, acc0); acc1 = fmaf(xv.y, w1v.y, acc1);
            acc2 = fmaf(xv.y, w1v.z, acc2); acc3 = fmaf(xv.y, w1v.w, acc3);
            acc0 = fmaf(xv.z, w2v.x, acc0); acc1 = fmaf(xv.z, w2v.y, acc1);
            acc2 = fmaf(xv.z, w2v.z, acc2); acc3 = fmaf(xv.z, w2v.w, acc3);
            acc0 = fmaf(xv.w, w3.x, acc0); acc1 = fmaf(xv.w, w3.y, acc1);
            acc2 = fmaf(xv.w, w3.z, acc2); acc3 = fmaf(xv.w, w3.w, acc3);
        }
        hs[r * H + jg * 4 + 0] = fmaxf(acc0 + b1[jg * 4 + 0], 0.f);
        hs[r * H + jg * 4 + 1] = fmaxf(acc1 + b1[jg * 4 + 1], 0.f);
        hs[r * H + jg * 4 + 2] = fmaxf(acc2 + b1[jg * 4 + 2], 0.f);
        hs[r * H + jg * 4 + 3] = fmaxf(acc3 + b1[jg * 4 + 3], 0.f);
    }
    __syncthreads();

    // Phase C: pred col c = tid across 32 rows.
    const int c = tid;
    float p[MR];
    {
        const float bb = b2[c];
#pragma unroll
        for (int r = 0; r < MR; r++) p[r] = bb;
        for (int jq = 0; jq < 16; jq++) {
            const float w0 = W2s[(jq * 4 + 0) * D + c];
            const float w1v = W2s[(jq * 4 + 1) * D + c];
            const float w2v = W2s[(jq * 4 + 2) * D + c];
            const float w3 = W2s[(jq * 4 + 3) * D + c];
#pragma unroll
            for (int r = 0; r < MR; r++) {
                const float4 h4 = *(const float4*)&hs[r * H + jq * 4];
                p[r] = fmaf(h4.x, w0, p[r]);
                p[r] = fmaf(h4.y, w1v, p[r]);
                p[r] = fmaf(h4.z, w2v, p[r]);
                p[r] = fmaf(h4.w, w3, p[r]);
            }
        }
    }
    __syncthreads();   // everyone done reading W1s before ss/qq alias writes
#pragma unroll
    for (int r = 0; r < MR; r++) {
        ss[r * D + c] = p[r] * p[r];
        qq[r * D + c] = p[r] * g_tn32[(size_t)(row0 + r) * D + c];
    }
    __syncthreads();

    // row reductions: warp w handles rows w*4 .. w*4+3
    {
        const int wid = tid >> 5, lane = tid & 31;
#pragma unroll
        for (int m = 0; m < 4; m++) {
            const int r = wid * 4 + m;
            float s1 = 0.f, s2 = 0.f;
#pragma unroll
            for (int s = 0; s < 8; s++) {
                s1 += ss[r * D + lane + 32 * s];
                s2 += qq[r * D + lane + 32 * s];
            }
#pragma unroll
            for (int o = 16; o > 0; o >>= 1) {
                s1 += __shfl_xor_sync(0xFFFFFFFF, s1, o);
                s2 += __shfl_xor_sync(0xFFFFFFFF, s2, o);
            }
            if (lane == 0) {
                invs[r] = 1.0f / fmaxf(sqrtf(s1), 1e-12f);
                dgs[r] = s2;
            }
        }
    }
    __syncthreads();

#pragma unroll
    for (int r = 0; r < MR; r++)
        g_pnb[(size_t)(row0 + r) * D + c] = __float2bfloat16(p[r] * invs[r]);
    if (tid < MR) g_diag[row0 + tid] = dgs[tid] * invs[tid];
}

// ---------------------------------------------------------------------------
// Kernel 3: bf16 mma.sync GEMM + fused per-row top-10.
// Grid 128 = 64 row-blocks x 2 column halves. 256 threads (4x2 warp grid,
// warp tile 32x64). A fragments cached in REGISTERS across all 32 tiles;
// A's SMEM region is recycled as one of two full-tile cp.async B buffers.
// ---------------------------------------------------------------------------
#define BM 128
#define BN 128
#define SSTR 264      // smem stride in halfs (528 B): conflict-free ldmatrix
#define CSTR 132      // C smem stride (floats)

extern __shared__ char dsm[];
__global__ __launch_bounds__(256) void gemm_topk_kernel() {
    const int tid = threadIdx.x;
    const int wid = tid >> 5, lane = tid & 31;
    const int wr = wid >> 1, wc = wid & 1;       // 4 x 2 warps, tile 32x64
    const int bx = blockIdx.x;
    const int row0 = (bx >> 1) * BM;
    const int half = bx & 1;
    const int cbeg = half * 4096;

    const uint32_t R1_a = smem_u32(dsm);          // A (prologue), then odd B buf
    const uint32_t R2_a = R1_a + 67584;           // even B buf
    float* Cs = (float*)(dsm + 135168);           // 67584 B
    __nv_bfloat16* R1p = (__nv_bfloat16*)dsm;

    // cp.async one full B tile (128 targets x 256 K bf16) into a buffer.
    auto issue_tile = [&](int tile, uint32_t buf_a) {
        if (tile < 32) {
            const __nv_bfloat16* srcb = g_tnb + (size_t)(cbeg + tile * BN) * D;
#pragma unroll
            for (int it = 0; it < 16; it++) {
                const int lin = it * 256 + tid;          // 0..4095
                const int r = lin >> 5, c16 = lin & 31;
                CP_ASYNC16(buf_a + (uint32_t)(r * SSTR + c16 * 8) * 2,
                           srcb + r * D + c16 * 8);
            }
        }
        CP_COMMIT();
    };

    // Commit order matters: B(0) first, B(1) second.
    issue_tile(0, R2_a);         // tile 0 -> even buffer (overlaps A prologue)

    // A prologue: load 128x256 bf16 into region1, then cache fragments in regs.
    {
        const uint4* src = (const uint4*)(g_pnb + (size_t)row0 * D);
#pragma unroll
        for (int it = 0; it < 16; it++) {
            const int lin = it * 256 + tid;
            const int r = lin >> 5, c16 = lin & 31;
            *(uint4*)(R1p + r * SSTR + c16 * 8) = src[lin];
        }
    }
    __syncthreads();

    const int a_row_off = (lane & 7) + ((lane >> 3) & 1) * 8;
    const int a_k_off   = (lane >> 4) * 8;
    const int b_col_off = (lane & 7) + ((lane >> 4) & 1) * 8;
    const int b_k_off   = ((lane >> 3) & 1) * 8;

    uint32_t aFrag[2][16][4];    // 128 regs: warp's 32 rows x full K
#pragma unroll
    for (int mi = 0; mi < 2; mi++) {
        const uint32_t ab = R1_a +
            (uint32_t)((wr * 32 + mi * 16 + a_row_off) * SSTR + a_k_off) * 2;
#pragma unroll
        for (int ks = 0; ks < 16; ks++)
            ldmatrix_x4(aFrag[mi][ks][0], aFrag[mi][ks][1],
                        aFrag[mi][ks][2], aFrag[mi][ks][3], ab + ks * 32);
    }
    __syncthreads();             // all warps done reading A region
    issue_tile(1, R1_a);         // tile 1 -> region1 (A region now free)

    // scan assignment: thread owns (row = tid&127, 64-col half = tid>>7)
    const int srow = tid & 127;
    const int shalf = tid >> 7;
    const int my_row = row0 + srow;
    float top[10];
#pragma unroll
    for (int q = 0; q < 10; q++) top[q] = -1e30f;

    float acc[2][8][4];

    for (int t = 0; t < 32; t++) {
        const int c0 = cbeg + t * BN;
        const uint32_t buf_a = (t & 1) ? R1_a : R2_a;

        if (t == 31) { CP_WAIT0(); } else { CP_WAIT1(); }   // B(t) complete
        __syncthreads();

#pragma unroll
        for (int mi = 0; mi < 2; mi++)
#pragma unroll
            for (int ni = 0; ni < 8; ni++)
#pragma unroll
                for (int q = 0; q < 4; q++) acc[mi][ni][q] = 0.f;

        // 16 K-steps; B frags via 4 ldmatrix_x4 per step (64 cols), A from regs
        {
            const uint32_t bb = buf_a +
                (uint32_t)((wc * 64 + b_col_off) * SSTR + b_k_off) * 2;
#pragma unroll
            for (int ks = 0; ks < 16; ks++) {
                uint32_t b[8][2];
#pragma unroll
                for (int g = 0; g < 4; g++) {
                    uint32_t r0, r1, r2, r3;
                    ldmatrix_x4(r0, r1, r2, r3,
                                bb + (uint32_t)(g * 16 * SSTR) * 2 + ks * 32);
                    b[g * 2 + 0][0] = r0; b[g * 2 + 0][1] = r1;
                    b[g * 2 + 1][0] = r2; b[g * 2 + 1][1] = r3;
                }
#pragma unroll
                for (int mi = 0; mi < 2; mi++)
#pragma unroll
                    for (int ni = 0; ni < 8; ni++)
                        mma_bf16(acc[mi][ni], aFrag[mi][ks], b[ni]);
            }
        }
        __syncthreads();                 // all warps done reading buf_a
        issue_tile(t + 2, buf_a);        // prefetch tile t+2 into same buffer

        // Write C tile (DMA runs underneath)
        {
            const int r0l = wr * 32 + (lane >> 2);
            const int c0l = wc * 64 + (lane & 3) * 2;
#pragma unroll
            for (int mi = 0; mi < 2; mi++)
#pragma unroll
                for (int ni = 0; ni < 8; ni++) {
                    float* p0 = Cs + (r0l + mi * 16) * CSTR + c0l + ni * 8;
                    p0[0] = acc[mi][ni][0]; p0[1] = acc[mi][ni][1];
                    float* p1 = p0 + 8 * CSTR;
                    p1[0] = acc[mi][ni][2]; p1[1] = acc[mi][ni][3];
                }
        }
        __syncthreads();

        // Scan: each thread scans 64 cols of its row, staggered start
        {
            const float* rowp = Cs + srow * CSTR + shalf * 64;
            const int jb = c0 + shalf * 64;
#pragma unroll 4
            for (int i = 0; i < 64; i++) {
                const int cl = (srow + i) & 63;
                const float v = rowp[cl];
                if (v > top[9] && (jb + cl) != my_row) {
                    top[9] = v;
#pragma unroll
                    for (int pq = 9; pq > 0; pq--) {
                        if (top[pq] > top[pq - 1]) {
                            const float tmp = top[pq - 1];
                            top[pq - 1] = top[pq];
                            top[pq] = tmp;
                        }
                    }
                }
            }
        }
        // next iteration's post-wait __syncthreads orders scan before C overwrite
    }

    // Merge the two per-row 64-col lists via Cs scratch
    __syncthreads();
    float* lists = Cs;                      // 256 * 10 floats
#pragma unroll
    for (int q = 0; q < 10; q++) lists[tid * 10 + q] = top[q];
    __syncthreads();
    if (tid < 128) {
        const float* la = lists + tid * 10;
        const float* lb = lists + (tid + 128) * 10;
        float out[10];
        int ia = 0, ib = 0;
#pragma unroll
        for (int q = 0; q < 10; q++) {
            const float va = la[ia], vb = lb[ib];
            if (va >= vb) { out[q] = va; ia++; }
            else          { out[q] = vb; ib++; }
        }
        float* dst = g_part + ((size_t)half * N + row0 + tid) * 10;
#pragma unroll
        for (int q = 0; q < 10; q++) dst[q] = out[q];
    }
}

// ---------------------------------------------------------------------------
// Kernel 4: merge per-half top-10 lists, form per-row loss term.
// ---------------------------------------------------------------------------
__global__ void terms_kernel() {
    const int i = blockIdx.x * blockDim.x + threadIdx.x;
    const float* a = g_part + (size_t)i * 10;
    const float* b = g_part + ((size_t)N + i) * 10;
    int ia = 0, ib = 0;
    float s9 = 0.0f;
#pragma unroll
    for (int r = 0; r < 10; r++) {
        float v;
        if (ib >= 10 || (ia < 10 && a[ia] >= b[ib])) v = a[ia++];
        else v = b[ib++];
        if (r > 0) s9 += v;
    }
    const float dist_an = (-2.0f / 9.0f) * s9;
    const float dist_ap = -2.0f * g_diag[i];
    g_terms[i] = fmaxf(0.0f, GAMMA * dist_ap - dist_an + MARGIN);
}

// ---------------------------------------------------------------------------
// Kernel 5: deterministic fixed-order mean reduction.
// ---------------------------------------------------------------------------
__global__ void reduce_kernel(float* __restrict__ out) {
    __shared__ float red[256];
    const int t = threadIdx.x;
    float s = 0.0f;
    for (int i = t; i < N; i += 256) s += g_terms[i];
    red[t] = s;
    __syncthreads();
#pragma unroll
    for (int sft = 128; sft > 0; sft >>= 1) {
        if (t < sft) red[t] += red[t + sft];
        __syncthreads();
    }
    if (t == 0) out[0] = red[0] / (float)N;
}

// ---------------------------------------------------------------------------
extern "C" void kernel_launch(void* const* d_in, const int* in_sizes, int n_in,
                              void* d_out, int out_size) {
    const float* input  = (const float*)d_in[0];
    const float* target = (const float*)d_in[1];
    const float* W1     = (const float*)d_in[2];
    const float* b1     = (const float*)d_in[3];
    const float* W2     = (const float*)d_in[4];
    const float* b2     = (const float*)d_in[5];
    float* out = (float*)d_out;

    cudaFuncSetAttribute(mlp_kernel, cudaFuncAttributeMaxDynamicSharedMemorySize, 172032);
    cudaFuncSetAttribute(gemm_topk_kernel, cudaFuncAttributeMaxDynamicSharedMemorySize, 202752);

    // Split norm into 2 launches so the GEMM is launch #4 (ncu captures #4).
    target_norm_kernel<<<N / 16, 256>>>(target, 0);
    target_norm_kernel<<<N / 16, 256>>>(target, N / 2);
    mlp_kernel<<<N / MR, 256, 172032>>>(input, W1, b1, W2, b2);
    gemm_topk_kernel<<<128, 256, 202752>>>();
    terms_kernel<<<N / 256, 256>>>();
    reduce_kernel<<<1, 256>>>(out);
}